// round 4
// baseline (speedup 1.0000x reference)
#include <cuda_runtime.h>
#include <cuda_bf16.h>
#include <math.h>

// Problem dims
#define Bb   64
#define Ss   512
#define Tt   64
#define Hh   512
#define Dd   512
#define G3   1536          // 3*H
#define HB   (Hh*Bb)       // 32768, one hidden state in [j][b] layout

// ---------------------------------------------------------------------------
// Scratch (device globals; no allocations allowed)
// ---------------------------------------------------------------------------
__device__ __align__(16) float g_gi[2][(size_t)Bb*Ss*G3];   // pre/post gate inputs [b][s][g]
__device__ __align__(16) float g_gid[(size_t)Bb*Tt*G3];     // decoder gate inputs  [b][t][g]
__device__ __align__(16) float g_hist[2][(size_t)(Ss+1)*HB];// encoder h history [t][j][b]
__device__ __align__(16) float g_dhist[(size_t)(Tt+1)*HB];  // decoder h history [t][j][b]
__device__ __align__(16) float g_score[Bb*2*Ss];            // score_enc [b][s2]
__device__ __align__(16) float g_hsc[Tt*Bb];                // decoder hidden scores [t][b]
__device__ int   g_dtok[Bb*Tt];                              // decoder input tokens

// ---------------------------------------------------------------------------
// init: zero h0 for both encoder GRUs
// ---------------------------------------------------------------------------
__global__ void init_kernel() {
    int i = blockIdx.x * blockDim.x + threadIdx.x;   // grid covers HB
    if (i < HB) { g_hist[0][i] = 0.f; g_hist[1][i] = 0.f; }
}

// ---------------------------------------------------------------------------
// decoder tokens: [pre_seq[:, -1:], trg[:, :-1]]
// ---------------------------------------------------------------------------
__global__ void dectok_kernel(const int* __restrict__ pre_seq,
                              const int* __restrict__ trg) {
    int idx = blockIdx.x * blockDim.x + threadIdx.x;   // 0..4095
    if (idx >= Bb * Tt) return;
    int b = idx >> 6, t = idx & 63;
    g_dtok[idx] = (t == 0) ? pre_seq[b * Ss + (Ss - 1)] : trg[b * Tt + t - 1];
}

// ---------------------------------------------------------------------------
// Fused gather-GEMM:  C[m][n] = sum_k emb[token[m]][k] * W[n][k] + bias[n]
// Tiles: 64x64x32, 256 threads, 4x4 microtile. dst: 0=gi_pre 1=gi_post 2=gi_dec
// ---------------------------------------------------------------------------
__global__ __launch_bounds__(256) void gemm_gather(
    const int* __restrict__ tokens_arg, int dst,
    const float* __restrict__ emb,
    const float* __restrict__ W,
    const float* __restrict__ bias)
{
    const int* tokens = (dst == 2) ? g_dtok : tokens_arg;
    float* C = (dst == 0) ? g_gi[0] : (dst == 1) ? g_gi[1] : g_gid;

    __shared__ __align__(16) float As[32 * 68];
    __shared__ __align__(16) float Bs[32 * 68];

    int tid = threadIdx.x;
    int m0 = blockIdx.x * 64;
    int n0 = blockIdx.y * 64;

    int lr = tid >> 3;            // 0..31
    int lc = (tid & 7) << 2;      // 0,4,...,28

    int tok0 = tokens[m0 + lr];
    int tok1 = tokens[m0 + lr + 32];
    const float* arow0 = emb + (size_t)tok0 * Dd;
    const float* arow1 = emb + (size_t)tok1 * Dd;
    const float* brow0 = W + (size_t)(n0 + lr) * Dd;
    const float* brow1 = W + (size_t)(n0 + lr + 32) * Dd;

    int tx = tid & 15, ty = tid >> 4;
    float acc[4][4];
    #pragma unroll
    for (int i = 0; i < 4; i++)
        #pragma unroll
        for (int j = 0; j < 4; j++) acc[i][j] = 0.f;

    for (int k0 = 0; k0 < Dd; k0 += 32) {
        float4 a0 = *(const float4*)(arow0 + k0 + lc);
        float4 a1 = *(const float4*)(arow1 + k0 + lc);
        float4 b0 = *(const float4*)(brow0 + k0 + lc);
        float4 b1 = *(const float4*)(brow1 + k0 + lc);
        __syncthreads();
        As[(lc + 0) * 68 + lr] = a0.x; As[(lc + 1) * 68 + lr] = a0.y;
        As[(lc + 2) * 68 + lr] = a0.z; As[(lc + 3) * 68 + lr] = a0.w;
        As[(lc + 0) * 68 + lr + 32] = a1.x; As[(lc + 1) * 68 + lr + 32] = a1.y;
        As[(lc + 2) * 68 + lr + 32] = a1.z; As[(lc + 3) * 68 + lr + 32] = a1.w;
        Bs[(lc + 0) * 68 + lr] = b0.x; Bs[(lc + 1) * 68 + lr] = b0.y;
        Bs[(lc + 2) * 68 + lr] = b0.z; Bs[(lc + 3) * 68 + lr] = b0.w;
        Bs[(lc + 0) * 68 + lr + 32] = b1.x; Bs[(lc + 1) * 68 + lr + 32] = b1.y;
        Bs[(lc + 2) * 68 + lr + 32] = b1.z; Bs[(lc + 3) * 68 + lr + 32] = b1.w;
        __syncthreads();
        #pragma unroll
        for (int kk = 0; kk < 32; kk++) {
            float4 av = *(const float4*)&As[kk * 68 + ty * 4];
            float4 bv = *(const float4*)&Bs[kk * 68 + tx * 4];
            float a[4] = {av.x, av.y, av.z, av.w};
            float b[4] = {bv.x, bv.y, bv.z, bv.w};
            #pragma unroll
            for (int i = 0; i < 4; i++)
                #pragma unroll
                for (int j = 0; j < 4; j++) acc[i][j] += a[i] * b[j];
        }
    }

    int n = n0 + tx * 4;
    float4 bo = *(const float4*)(bias + n);
    float bb[4] = {bo.x, bo.y, bo.z, bo.w};
    #pragma unroll
    for (int i = 0; i < 4; i++) {
        int m = m0 + ty * 4 + i;
        float4 o;
        o.x = acc[i][0] + bb[0];
        o.y = acc[i][1] + bb[1];
        o.z = acc[i][2] + bb[2];
        o.w = acc[i][3] + bb[3];
        *(float4*)&C[(size_t)m * G3 + n] = o;
    }
}

// ---------------------------------------------------------------------------
// GRU step: computes h_{t+1} for (optionally two) GRUs.
// CTA owns 8 h-columns; Whh slice (24 rows x 512) staged in smem (48KB).
// Thread: jj = tid>>4 (0..7), bg = tid&15 -> 4 batches (bg*4..bg*4+3).
// h layout [j][b] (j-major), so h reads are LDG.128-coalesced.
// ---------------------------------------------------------------------------
#define FMA4(hv, wrv, wzv, wnv)                                               \
    accr[0] += hv.x * wrv; accr[1] += hv.y * wrv;                             \
    accr[2] += hv.z * wrv; accr[3] += hv.w * wrv;                             \
    accz[0] += hv.x * wzv; accz[1] += hv.y * wzv;                             \
    accz[2] += hv.z * wzv; accz[3] += hv.w * wzv;                             \
    accn[0] += hv.x * wnv; accn[1] += hv.y * wnv;                             \
    accn[2] += hv.z * wnv; accn[3] += hv.w * wnv;

__global__ __launch_bounds__(128) void gru_step(
    int isDec, int t,
    const float* __restrict__ Whh0, const float* __restrict__ Whh1,
    const float* __restrict__ bhh0, const float* __restrict__ bhh1)
{
    int gru = blockIdx.y;
    const float* gi  = isDec ? g_gid : g_gi[gru];
    float* hist      = isDec ? g_dhist : g_hist[gru];
    const float* Whh = gru ? Whh1 : Whh0;
    const float* bhh = gru ? bhh1 : bhh0;
    int seq = isDec ? Tt : Ss;

    const float* h_in = hist + (size_t)t * HB;
    float* h_out      = hist + (size_t)(t + 1) * HB;

    __shared__ __align__(16) float sw[24 * 512];   // exactly 48KB
    int tid = threadIdx.x;
    int j0 = blockIdx.x * 8;
    {
        const float4* W4 = (const float4*)Whh;
        float4* sw4 = (float4*)sw;
        #pragma unroll
        for (int r = 0; r < 24; r++) {
            int gate = r >> 3, jj = r & 7;
            int row = gate * Hh + j0 + jj;
            sw4[r * 128 + tid] = W4[(size_t)row * 128 + tid];
        }
    }
    __syncthreads();

    int jj = tid >> 4;
    int bg = tid & 15;
    const float4* h4  = (const float4*)h_in;
    const float4* swr = (const float4*)(sw + jj * 512);
    const float4* swz = (const float4*)(sw + (8 + jj) * 512);
    const float4* swn = (const float4*)(sw + (16 + jj) * 512);

    float accr[4] = {0.f, 0.f, 0.f, 0.f};
    float accz[4] = {0.f, 0.f, 0.f, 0.f};
    float accn[4] = {0.f, 0.f, 0.f, 0.f};

    #pragma unroll 4
    for (int k4 = 0; k4 < 128; k4++) {
        float4 wr = swr[k4], wz = swz[k4], wn = swn[k4];
        float4 hA = h4[(k4 * 4 + 0) * 16 + bg];
        float4 hB = h4[(k4 * 4 + 1) * 16 + bg];
        float4 hC = h4[(k4 * 4 + 2) * 16 + bg];
        float4 hD = h4[(k4 * 4 + 3) * 16 + bg];
        FMA4(hA, wr.x, wz.x, wn.x)
        FMA4(hB, wr.y, wz.y, wn.y)
        FMA4(hC, wr.z, wz.z, wn.z)
        FMA4(hD, wr.w, wz.w, wn.w)
    }

    int j = j0 + jj;
    float br = bhh[j], bz = bhh[Hh + j], bn = bhh[2 * Hh + j];
    float4 hold4 = h4[j * 16 + bg];
    float holdv[4] = {hold4.x, hold4.y, hold4.z, hold4.w};
    float ho[4];
    #pragma unroll
    for (int i = 0; i < 4; i++) {
        int b = bg * 4 + i;
        const float* g = gi + ((size_t)b * seq + t) * G3;
        float r = 1.f / (1.f + expf(-(g[j]          + accr[i] + br)));
        float z = 1.f / (1.f + expf(-(g[Hh + j]     + accz[i] + bz)));
        float n = tanhf(g[2 * Hh + j] + r * (accn[i] + bn));
        ho[i] = (1.f - z) * n + z * holdv[i];
    }
    *(float4*)&h_out[j * Bb + bg * 4] = make_float4(ho[0], ho[1], ho[2], ho[3]);
}

// ---------------------------------------------------------------------------
// score_enc[b][gru*S + t] = sum_j relu(h_{t+1}[j][b]) * w_enc[j]
// CTA = (t, gru), 64 threads (one per b)
// ---------------------------------------------------------------------------
__global__ __launch_bounds__(64) void score_kernel(const float* __restrict__ out_w) {
    int t = blockIdx.x, gru = blockIdx.y, b = threadIdx.x;
    const float* hrow = g_hist[gru] + (size_t)(t + 1) * HB;
    float acc = 0.f;
    for (int j = 0; j < Hh; j++)
        acc += fmaxf(hrow[j * Bb + b], 0.f) * out_w[j];
    g_score[b * (2 * Ss) + gru * Ss + t] = acc;
}

// ---------------------------------------------------------------------------
// enc_hidden (decoder h0) = tanh(cat(pre_h, post_h) @ enc_fc_w^T + enc_fc_b)
// CTA = i (output column, 0..511), 64 threads (one per b). Writes g_dhist[0].
// ---------------------------------------------------------------------------
__global__ __launch_bounds__(64) void ench_kernel(const float* __restrict__ enc_fc_w,
                                                  const float* __restrict__ enc_fc_b) {
    int i = blockIdx.x, b = threadIdx.x;
    const float* w = enc_fc_w + (size_t)i * (2 * Hh);
    const float* hp0 = g_hist[0] + (size_t)Ss * HB;
    const float* hp1 = g_hist[1] + (size_t)Ss * HB;
    float acc = enc_fc_b[i];
    for (int q = 0; q < Hh; q++) acc += hp0[q * Bb + b] * w[q];
    for (int q = 0; q < Hh; q++) acc += hp1[q * Bb + b] * w[Hh + q];
    g_dhist[i * Bb + b] = tanhf(acc);
}

// ---------------------------------------------------------------------------
// decoder hidden score: hsc[t][b] = relu(hdec_{t+1}[:,b]) . w_hid + out_b
// ---------------------------------------------------------------------------
__global__ __launch_bounds__(64) void hsc_kernel(const float* __restrict__ out_w,
                                                 const float* __restrict__ out_b) {
    int t = blockIdx.x, b = threadIdx.x;
    const float* hrow = g_dhist + (size_t)(t + 1) * HB;
    float acc = 0.f;
    for (int j = 0; j < Hh; j++)
        acc += fmaxf(hrow[j * Bb + b], 0.f) * out_w[Hh + j];
    g_hsc[t * Bb + b] = acc + out_b[0];
}

// ---------------------------------------------------------------------------
// probs: out_pre[b][t][s] = sigmoid(score[b][s]      + hsc[t][b])
//        out_post[b][t][s] = sigmoid(score[b][S + s] + hsc[t][b])
// CTA = bt (b*T + t), 256 threads x 4 iters over s2 = 0..1023
// ---------------------------------------------------------------------------
__global__ __launch_bounds__(256) void probs_kernel(float* __restrict__ out) {
    int bt = blockIdx.x;             // 0..4095
    int b = bt >> 6, t = bt & 63;
    float hs = g_hsc[t * Bb + b];
    const float* sc = g_score + b * (2 * Ss);
    float* out_pre  = out + (size_t)bt * Ss;
    float* out_post = out + (size_t)Bb * Tt * Ss + (size_t)bt * Ss;
    #pragma unroll
    for (int it = 0; it < 4; it++) {
        int s2 = it * 256 + threadIdx.x;
        float l = sc[s2] + hs;
        float p = 1.f / (1.f + expf(-l));
        if (s2 < Ss) out_pre[s2] = p;
        else         out_post[s2 - Ss] = p;
    }
}

// ---------------------------------------------------------------------------
// launch
// ---------------------------------------------------------------------------
extern "C" void kernel_launch(void* const* d_in, const int* in_sizes, int n_in,
                              void* d_out, int out_size) {
    const int*   pre_seq   = (const int*)  d_in[0];
    const int*   post_seq  = (const int*)  d_in[1];
    const int*   trg       = (const int*)  d_in[2];
    const float* emb       = (const float*)d_in[3];
    const float* pre_Wih   = (const float*)d_in[4];
    const float* pre_Whh   = (const float*)d_in[5];
    const float* pre_bih   = (const float*)d_in[6];
    const float* pre_bhh   = (const float*)d_in[7];
    const float* post_Wih  = (const float*)d_in[8];
    const float* post_Whh  = (const float*)d_in[9];
    const float* post_bih  = (const float*)d_in[10];
    const float* post_bhh  = (const float*)d_in[11];
    const float* enc_fc_w  = (const float*)d_in[12];
    const float* enc_fc_b  = (const float*)d_in[13];
    const float* dec_Wih   = (const float*)d_in[14];
    const float* dec_Whh   = (const float*)d_in[15];
    const float* dec_bih   = (const float*)d_in[16];
    const float* dec_bhh   = (const float*)d_in[17];
    const float* out_w     = (const float*)d_in[18];
    const float* out_b     = (const float*)d_in[19];
    float* out = (float*)d_out;

    // h0 = 0 and decoder token assembly
    init_kernel<<<128, 256>>>();
    dectok_kernel<<<16, 256>>>(pre_seq, trg);

    // Gate-input GEMMs (fused embedding gather): gi = emb[tok] @ Wih^T + bih
    gemm_gather<<<dim3(Bb * Ss / 64, G3 / 64), 256>>>(pre_seq,  0, emb, pre_Wih,  pre_bih);
    gemm_gather<<<dim3(Bb * Ss / 64, G3 / 64), 256>>>(post_seq, 1, emb, post_Wih, post_bih);
    gemm_gather<<<dim3(Bb * Tt / 64, G3 / 64), 256>>>(nullptr,  2, emb, dec_Wih,  dec_bih);

    // Encoder recurrences (pre + post in one grid per step)
    for (int t = 0; t < Ss; t++)
        gru_step<<<dim3(Hh / 8, 2), 128>>>(0, t, pre_Whh, post_Whh, pre_bhh, post_bhh);

    // score_enc over all encoder outputs; decoder initial hidden
    score_kernel<<<dim3(Ss, 2), 64>>>(out_w);
    ench_kernel<<<Hh, 64>>>(enc_fc_w, enc_fc_b);

    // Decoder recurrence
    for (int t = 0; t < Tt; t++)
        gru_step<<<dim3(Hh / 8, 1), 128>>>(1, t, dec_Whh, dec_Whh, dec_bhh, dec_bhh);

    // Logits -> probabilities -> output
    hsc_kernel<<<Tt, 64>>>(out_w, out_b);
    probs_kernel<<<Bb * Tt, 256>>>(out);
}

// round 5
// speedup vs baseline: 1.1356x; 1.1356x over previous
#include <cuda_runtime.h>
#include <cuda_bf16.h>
#include <math.h>

// Problem dims
#define Bb   64
#define Ss   512
#define Tt   64
#define Hh   512
#define Dd   512
#define G3   1536          // 3*H
#define HB   (Hh*Bb)       // 32768, one hidden state in [j][b] layout

// ---------------------------------------------------------------------------
// Scratch (device globals; no allocations allowed)
// ---------------------------------------------------------------------------
__device__ __align__(16) float g_gi[2][(size_t)Bb*Ss*G3];   // pre/post gate inputs [b][s][g]
__device__ __align__(16) float g_gid[(size_t)Bb*Tt*G3];     // decoder gate inputs  [b][t][g]
__device__ __align__(16) float g_hist[2][(size_t)(Ss+1)*HB];// encoder h history [t][j][b]
__device__ __align__(16) float g_dhist[(size_t)(Tt+1)*HB];  // decoder h history [t][j][b]
__device__ __align__(16) float g_score[Bb*2*Ss];            // score_enc [b][s2]
__device__ __align__(16) float g_hsc[Tt*Bb];                // decoder hidden scores [t][b]
__device__ int   g_dtok[Bb*Tt];                              // decoder input tokens

// ---------------------------------------------------------------------------
// init: zero h0 for both encoder GRUs
// ---------------------------------------------------------------------------
__global__ void init_kernel() {
    int i = blockIdx.x * blockDim.x + threadIdx.x;   // grid covers HB
    if (i < HB) { g_hist[0][i] = 0.f; g_hist[1][i] = 0.f; }
}

// ---------------------------------------------------------------------------
// decoder tokens: [pre_seq[:, -1:], trg[:, :-1]]
// ---------------------------------------------------------------------------
__global__ void dectok_kernel(const int* __restrict__ pre_seq,
                              const int* __restrict__ trg) {
    int idx = blockIdx.x * blockDim.x + threadIdx.x;   // 0..4095
    if (idx >= Bb * Tt) return;
    int b = idx >> 6, t = idx & 63;
    g_dtok[idx] = (t == 0) ? pre_seq[b * Ss + (Ss - 1)] : trg[b * Tt + t - 1];
}

// ---------------------------------------------------------------------------
// Fused gather-GEMM:  C[m][n] = sum_k emb[token[m]][k] * W[n][k] + bias[n]
// Tiles: 128x128x16, 256 threads, 8x8 microtile.
// dst: 0=gi_pre 1=gi_post 2=gi_dec
// ---------------------------------------------------------------------------
#define BK 16
__global__ __launch_bounds__(256, 2) void gemm_gather(
    const int* __restrict__ tokens_arg, int dst,
    const float* __restrict__ emb,
    const float* __restrict__ W,
    const float* __restrict__ bias)
{
    const int* tokens = (dst == 2) ? g_dtok : tokens_arg;
    float* C = (dst == 0) ? g_gi[0] : (dst == 1) ? g_gi[1] : g_gid;

    __shared__ __align__(16) float As[BK][128];
    __shared__ __align__(16) float Bs[BK][128];

    int tid = threadIdx.x;
    int m0 = blockIdx.x * 128;
    int n0 = blockIdx.y * 128;

    // staging assignment: 128 rows x 16 k per tile; thread loads 2x float4
    int lrow = tid >> 1;            // 0..127
    int lcol = (tid & 1) << 2;      // 0 or 4

    int tok = tokens[m0 + lrow];
    const float* arow = emb + (size_t)tok * Dd + lcol;
    const float* brow = W + (size_t)(n0 + lrow) * Dd + lcol;

    int tx = tid & 15;              // n microtile (8 cols)
    int ty = tid >> 4;              // m microtile (8 rows)

    float acc[8][8];
    #pragma unroll
    for (int i = 0; i < 8; i++)
        #pragma unroll
        for (int j = 0; j < 8; j++) acc[i][j] = 0.f;

    for (int k0 = 0; k0 < Dd; k0 += BK) {
        float4 a0 = *(const float4*)(arow + k0);
        float4 a1 = *(const float4*)(arow + k0 + 8);
        float4 b0 = *(const float4*)(brow + k0);
        float4 b1 = *(const float4*)(brow + k0 + 8);
        __syncthreads();
        As[lcol + 0][lrow] = a0.x; As[lcol + 1][lrow] = a0.y;
        As[lcol + 2][lrow] = a0.z; As[lcol + 3][lrow] = a0.w;
        As[lcol + 8][lrow] = a1.x; As[lcol + 9][lrow] = a1.y;
        As[lcol +10][lrow] = a1.z; As[lcol +11][lrow] = a1.w;
        Bs[lcol + 0][lrow] = b0.x; Bs[lcol + 1][lrow] = b0.y;
        Bs[lcol + 2][lrow] = b0.z; Bs[lcol + 3][lrow] = b0.w;
        Bs[lcol + 8][lrow] = b1.x; Bs[lcol + 9][lrow] = b1.y;
        Bs[lcol +10][lrow] = b1.z; Bs[lcol +11][lrow] = b1.w;
        __syncthreads();
        #pragma unroll
        for (int kk = 0; kk < BK; kk++) {
            float4 av0 = *(const float4*)&As[kk][ty * 8];
            float4 av1 = *(const float4*)&As[kk][ty * 8 + 4];
            float4 bv0 = *(const float4*)&Bs[kk][tx * 8];
            float4 bv1 = *(const float4*)&Bs[kk][tx * 8 + 4];
            float a[8] = {av0.x, av0.y, av0.z, av0.w, av1.x, av1.y, av1.z, av1.w};
            float b[8] = {bv0.x, bv0.y, bv0.z, bv0.w, bv1.x, bv1.y, bv1.z, bv1.w};
            #pragma unroll
            for (int i = 0; i < 8; i++)
                #pragma unroll
                for (int j = 0; j < 8; j++) acc[i][j] += a[i] * b[j];
        }
    }

    int n = n0 + tx * 8;
    float4 bo0 = *(const float4*)(bias + n);
    float4 bo1 = *(const float4*)(bias + n + 4);
    float bb[8] = {bo0.x, bo0.y, bo0.z, bo0.w, bo1.x, bo1.y, bo1.z, bo1.w};
    #pragma unroll
    for (int i = 0; i < 8; i++) {
        int m = m0 + ty * 8 + i;
        float4 o0, o1;
        o0.x = acc[i][0] + bb[0]; o0.y = acc[i][1] + bb[1];
        o0.z = acc[i][2] + bb[2]; o0.w = acc[i][3] + bb[3];
        o1.x = acc[i][4] + bb[4]; o1.y = acc[i][5] + bb[5];
        o1.z = acc[i][6] + bb[6]; o1.w = acc[i][7] + bb[7];
        *(float4*)&C[(size_t)m * G3 + n]     = o0;
        *(float4*)&C[(size_t)m * G3 + n + 4] = o1;
    }
}

// ---------------------------------------------------------------------------
// GRU step: computes h_{t+1} for (optionally two) GRUs.
// CTA owns 8 h-columns; Whh slice (24 rows x 512) staged in smem (48KB).
// 256 threads: jj = tid>>5 (0..7), bg = tid&31 -> 2 batches (bg*2, bg*2+1).
// h layout [j][b] (j-major), so h reads are coalesced.
// 2 warps/SMSP for latency hiding.
// ---------------------------------------------------------------------------
#define FMA2(hv, wrv, wzv, wnv)                                               \
    accr[0] += hv.x * wrv; accr[1] += hv.y * wrv;                             \
    accz[0] += hv.x * wzv; accz[1] += hv.y * wzv;                             \
    accn[0] += hv.x * wnv; accn[1] += hv.y * wnv;

__device__ __forceinline__ float fsigmoid(float x) {
    return 1.f / (1.f + __expf(-x));
}

__global__ __launch_bounds__(256) void gru_step(
    int isDec, int t,
    const float* __restrict__ Whh0, const float* __restrict__ Whh1,
    const float* __restrict__ bhh0, const float* __restrict__ bhh1)
{
    int gru = blockIdx.y;
    const float* gi  = isDec ? g_gid : g_gi[gru];
    float* hist      = isDec ? g_dhist : g_hist[gru];
    const float* Whh = gru ? Whh1 : Whh0;
    const float* bhh = gru ? bhh1 : bhh0;
    int seq = isDec ? Tt : Ss;

    const float* h_in = hist + (size_t)t * HB;
    float* h_out      = hist + (size_t)(t + 1) * HB;

    __shared__ __align__(16) float sw[24 * 512];   // exactly 48KB
    int tid = threadIdx.x;
    int j0 = blockIdx.x * 8;
    {
        const float4* W4 = (const float4*)Whh;
        float4* sw4 = (float4*)sw;
        #pragma unroll
        for (int i = 0; i < 12; i++) {
            int idx = i * 256 + tid;          // 0..3071 float4s
            int r = idx >> 7, c = idx & 127;
            int gate = r >> 3, jj = r & 7;
            int row = gate * Hh + j0 + jj;
            sw4[idx] = W4[(size_t)row * 128 + c];
        }
    }
    __syncthreads();

    int jj = tid >> 5;    // 0..7
    int bg = tid & 31;    // 0..31
    const float2* h2  = (const float2*)h_in;
    const float4* swr = (const float4*)(sw + jj * 512);
    const float4* swz = (const float4*)(sw + (8 + jj) * 512);
    const float4* swn = (const float4*)(sw + (16 + jj) * 512);

    float accr[2] = {0.f, 0.f};
    float accz[2] = {0.f, 0.f};
    float accn[2] = {0.f, 0.f};

    #pragma unroll 4
    for (int k4 = 0; k4 < 128; k4++) {
        float4 wr = swr[k4], wz = swz[k4], wn = swn[k4];
        float2 hA = h2[(k4 * 4 + 0) * 32 + bg];
        float2 hB = h2[(k4 * 4 + 1) * 32 + bg];
        float2 hC = h2[(k4 * 4 + 2) * 32 + bg];
        float2 hD = h2[(k4 * 4 + 3) * 32 + bg];
        FMA2(hA, wr.x, wz.x, wn.x)
        FMA2(hB, wr.y, wz.y, wn.y)
        FMA2(hC, wr.z, wz.z, wn.z)
        FMA2(hD, wr.w, wz.w, wn.w)
    }

    int j = j0 + jj;
    float br = bhh[j], bz = bhh[Hh + j], bn = bhh[2 * Hh + j];
    float2 hold = h2[j * 32 + bg];
    float holdv[2] = {hold.x, hold.y};
    float ho[2];
    #pragma unroll
    for (int i = 0; i < 2; i++) {
        int b = bg * 2 + i;
        const float* g = gi + ((size_t)b * seq + t) * G3;
        float r = fsigmoid(g[j]          + accr[i] + br);
        float z = fsigmoid(g[Hh + j]     + accz[i] + bz);
        float n = tanhf(g[2 * Hh + j] + r * (accn[i] + bn));
        ho[i] = (1.f - z) * n + z * holdv[i];
    }
    *(float2*)&h_out[j * Bb + bg * 2] = make_float2(ho[0], ho[1]);
}

// ---------------------------------------------------------------------------
// score_enc[b][gru*S + t] = sum_j relu(h_{t+1}[j][b]) * w_enc[j]
// CTA = (t, gru), 64 threads (one per b)
// ---------------------------------------------------------------------------
__global__ __launch_bounds__(64) void score_kernel(const float* __restrict__ out_w) {
    int t = blockIdx.x, gru = blockIdx.y, b = threadIdx.x;
    const float* hrow = g_hist[gru] + (size_t)(t + 1) * HB;
    float acc = 0.f;
    for (int j = 0; j < Hh; j++)
        acc += fmaxf(hrow[j * Bb + b], 0.f) * out_w[j];
    g_score[b * (2 * Ss) + gru * Ss + t] = acc;
}

// ---------------------------------------------------------------------------
// enc_hidden (decoder h0) = tanh(cat(pre_h, post_h) @ enc_fc_w^T + enc_fc_b)
// CTA = i (output column, 0..511), 64 threads (one per b). Writes g_dhist[0].
// ---------------------------------------------------------------------------
__global__ __launch_bounds__(64) void ench_kernel(const float* __restrict__ enc_fc_w,
                                                  const float* __restrict__ enc_fc_b) {
    int i = blockIdx.x, b = threadIdx.x;
    const float* w = enc_fc_w + (size_t)i * (2 * Hh);
    const float* hp0 = g_hist[0] + (size_t)Ss * HB;
    const float* hp1 = g_hist[1] + (size_t)Ss * HB;
    float acc = enc_fc_b[i];
    for (int q = 0; q < Hh; q++) acc += hp0[q * Bb + b] * w[q];
    for (int q = 0; q < Hh; q++) acc += hp1[q * Bb + b] * w[Hh + q];
    g_dhist[i * Bb + b] = tanhf(acc);
}

// ---------------------------------------------------------------------------
// decoder hidden score: hsc[t][b] = relu(hdec_{t+1}[:,b]) . w_hid + out_b
// ---------------------------------------------------------------------------
__global__ __launch_bounds__(64) void hsc_kernel(const float* __restrict__ out_w,
                                                 const float* __restrict__ out_b) {
    int t = blockIdx.x, b = threadIdx.x;
    const float* hrow = g_dhist + (size_t)(t + 1) * HB;
    float acc = 0.f;
    for (int j = 0; j < Hh; j++)
        acc += fmaxf(hrow[j * Bb + b], 0.f) * out_w[Hh + j];
    g_hsc[t * Bb + b] = acc + out_b[0];
}

// ---------------------------------------------------------------------------
// probs: out_pre[b][t][s] = sigmoid(score[b][s]      + hsc[t][b])
//        out_post[b][t][s] = sigmoid(score[b][S + s] + hsc[t][b])
// CTA = bt (b*T + t), 256 threads x 4 iters over s2 = 0..1023
// ---------------------------------------------------------------------------
__global__ __launch_bounds__(256) void probs_kernel(float* __restrict__ out) {
    int bt = blockIdx.x;             // 0..4095
    int b = bt >> 6, t = bt & 63;
    float hs = g_hsc[t * Bb + b];
    const float* sc = g_score + b * (2 * Ss);
    float* out_pre  = out + (size_t)bt * Ss;
    float* out_post = out + (size_t)Bb * Tt * Ss + (size_t)bt * Ss;
    #pragma unroll
    for (int it = 0; it < 4; it++) {
        int s2 = it * 256 + threadIdx.x;
        float l = sc[s2] + hs;
        float p = 1.f / (1.f + expf(-l));
        if (s2 < Ss) out_pre[s2] = p;
        else         out_post[s2 - Ss] = p;
    }
}

// ---------------------------------------------------------------------------
// launch
// ---------------------------------------------------------------------------
extern "C" void kernel_launch(void* const* d_in, const int* in_sizes, int n_in,
                              void* d_out, int out_size) {
    const int*   pre_seq   = (const int*)  d_in[0];
    const int*   post_seq  = (const int*)  d_in[1];
    const int*   trg       = (const int*)  d_in[2];
    const float* emb       = (const float*)d_in[3];
    const float* pre_Wih   = (const float*)d_in[4];
    const float* pre_Whh   = (const float*)d_in[5];
    const float* pre_bih   = (const float*)d_in[6];
    const float* pre_bhh   = (const float*)d_in[7];
    const float* post_Wih  = (const float*)d_in[8];
    const float* post_Whh  = (const float*)d_in[9];
    const float* post_bih  = (const float*)d_in[10];
    const float* post_bhh  = (const float*)d_in[11];
    const float* enc_fc_w  = (const float*)d_in[12];
    const float* enc_fc_b  = (const float*)d_in[13];
    const float* dec_Wih   = (const float*)d_in[14];
    const float* dec_Whh   = (const float*)d_in[15];
    const float* dec_bih   = (const float*)d_in[16];
    const float* dec_bhh   = (const float*)d_in[17];
    const float* out_w     = (const float*)d_in[18];
    const float* out_b     = (const float*)d_in[19];
    float* out = (float*)d_out;

    // h0 = 0 and decoder token assembly
    init_kernel<<<128, 256>>>();
    dectok_kernel<<<16, 256>>>(pre_seq, trg);

    // Gate-input GEMMs (fused embedding gather): gi = emb[tok] @ Wih^T + bih
    gemm_gather<<<dim3(Bb * Ss / 128, G3 / 128), 256>>>(pre_seq,  0, emb, pre_Wih,  pre_bih);
    gemm_gather<<<dim3(Bb * Ss / 128, G3 / 128), 256>>>(post_seq, 1, emb, post_Wih, post_bih);
    gemm_gather<<<dim3(Bb * Tt / 128, G3 / 128), 256>>>(nullptr,  2, emb, dec_Wih,  dec_bih);

    // Encoder recurrences (pre + post in one grid per step)
    for (int t = 0; t < Ss; t++)
        gru_step<<<dim3(Hh / 8, 2), 256>>>(0, t, pre_Whh, post_Whh, pre_bhh, post_bhh);

    // score_enc over all encoder outputs; decoder initial hidden
    score_kernel<<<dim3(Ss, 2), 64>>>(out_w);
    ench_kernel<<<Hh, 64>>>(enc_fc_w, enc_fc_b);

    // Decoder recurrence
    for (int t = 0; t < Tt; t++)
        gru_step<<<dim3(Hh / 8, 1), 256>>>(1, t, dec_Whh, dec_Whh, dec_bhh, dec_bhh);

    // Logits -> probabilities -> output
    hsc_kernel<<<Tt, 64>>>(out_w, out_b);
    probs_kernel<<<Bb * Tt, 256>>>(out);
}